// round 1
// baseline (speedup 1.0000x reference)
#include <cuda_runtime.h>
#include <cstddef>

#define N_MEM 8
#define BATCH 64
#define D_K 256
#define D_V 256

// out layout: new_states [N_MEM, B, D_K, D_V] followed by readouts [N_MEM, B, D_V]
#define STATES_ELEMS ((size_t)N_MEM * BATCH * D_K * D_V)

__global__ __launch_bounds__(256, 4)
void mom_fused_kernel(const float* __restrict__ states,
                      const float* __restrict__ key,
                      const float* __restrict__ value,
                      const float* __restrict__ alpha,
                      const float* __restrict__ rho,
                      const float* __restrict__ lam,
                      const float* __restrict__ query,
                      float* __restrict__ out_states,
                      float* __restrict__ out_read)
{
    // One CTA per (n, b) slice. blockIdx.x = n * BATCH + b
    const int nb = blockIdx.x;
    const int n  = nb / BATCH;
    const int b  = nb - n * BATCH;

    const int tx = threadIdx.x;   // 0..63  : D_V in float4 units
    const int ty = threadIdx.y;   // 0..3   : k-row partition
    const int tid = ty * 64 + tx; // 0..255

    const float lam_s = lam[b * N_MEM + n];
    const float w     = rho[b * N_MEM + n] * alpha[b];

    __shared__ float skey[D_K];
    __shared__ float sq[D_K];
    skey[tid] = key[b * D_K + tid] * w;   // pre-scale key by write strength
    sq[tid]   = query[b * D_K + tid];
    __syncthreads();

    const size_t slice = (size_t)nb * D_K * D_V;
    const float4* __restrict__ st  = (const float4*)(states + slice);
    float4* __restrict__       ost = (float4*)(out_states + slice);

    const float4 val4 = ((const float4*)(value + b * D_V))[tx];

    float4 acc = make_float4(0.f, 0.f, 0.f, 0.f);

    // Each thread: 64 k-rows (ty, ty+4, ...), one float4 of v per row.
    #pragma unroll 4
    for (int k = ty; k < D_K; k += 4) {
        float4 s = st[k * 64 + tx];
        const float kw = skey[k];
        float4 ns;
        ns.x = lam_s * s.x + kw * val4.x;
        ns.y = lam_s * s.y + kw * val4.y;
        ns.z = lam_s * s.z + kw * val4.z;
        ns.w = lam_s * s.w + kw * val4.w;
        ost[k * 64 + tx] = ns;
        const float q = sq[k];
        acc.x += q * ns.x;
        acc.y += q * ns.y;
        acc.z += q * ns.z;
        acc.w += q * ns.w;
    }

    // Cross-ty reduction of the readout partials
    __shared__ float4 red[4][64];
    red[ty][tx] = acc;
    __syncthreads();
    if (ty == 0) {
        float4 r0 = red[0][tx];
        float4 r1 = red[1][tx];
        float4 r2 = red[2][tx];
        float4 r3 = red[3][tx];
        float4 r;
        r.x = (r0.x + r1.x) + (r2.x + r3.x);
        r.y = (r0.y + r1.y) + (r2.y + r3.y);
        r.z = (r0.z + r1.z) + (r2.z + r3.z);
        r.w = (r0.w + r1.w) + (r2.w + r3.w);
        // readouts[n][b][v]: offset nb * D_V
        ((float4*)(out_read + (size_t)nb * D_V))[tx] = r;
    }
}

extern "C" void kernel_launch(void* const* d_in, const int* in_sizes, int n_in,
                              void* d_out, int out_size)
{
    const float* states = (const float*)d_in[0];
    const float* key    = (const float*)d_in[1];
    const float* value  = (const float*)d_in[2];
    const float* alpha  = (const float*)d_in[3];
    const float* rho    = (const float*)d_in[4];
    const float* lam    = (const float*)d_in[5];
    const float* query  = (const float*)d_in[6];

    float* out_states = (float*)d_out;
    float* out_read   = (float*)d_out + STATES_ELEMS;

    dim3 block(64, 4);
    dim3 grid(N_MEM * BATCH);
    mom_fused_kernel<<<grid, block>>>(states, key, value, alpha, rho, lam, query,
                                      out_states, out_read);
}